// round 3
// baseline (speedup 1.0000x reference)
#include <cuda_runtime.h>

#define NH 128
#define MAXG 16384
#define MAXP 524288

// ---------------- scratch (no allocations allowed) ----------------
__device__ __align__(16) float g_S[MAXG * NH];   // per-grid raw segment means
__device__ __align__(16) float g_U[MAXG * NH];   // per-grid u vectors
__device__ float g_C[MAXG];                      // per-grid scalar offset
__device__ int   g_off[MAXG + 1];                // exclusive prefix of grid_sizes
__device__ int   g_seg[MAXP];                    // seg id per pos sample
__device__ float g_B1[NH * NH];                  // Wk @ Wi
__device__ float g_kb[NH];                       // Wk @ bi
__device__ float g_q[NH];                        // bi^T Wk
__device__ __align__(16) float g_M[NH * NH];     // M[k*NH+d] = A[d][k], A = Wi^T Wk Wi
__device__ float g_v[NH];                        // Wi^T Wk bi
__device__ float g_w[NH];                        // Wi^T Wk^T bi
__device__ float g_c0;                           // bi^T Wk bi + bk

// ---------------- stage 0a: B1 = Wk@Wi, kb = Wk@bi, q = bi^T Wk ----
__global__ void small1_kernel(const float* __restrict__ Wi,
                              const float* __restrict__ Wk,
                              const float* __restrict__ bi) {
    int b = blockIdx.x;
    int t = threadIdx.x;
    if (b < NH) {
        int d = b;
        float acc = 0.f;
        #pragma unroll 4
        for (int e = 0; e < NH; e++)
            acc += __ldg(&Wk[d * NH + e]) * __ldg(&Wi[e * NH + t]);
        g_B1[d * NH + t] = acc;
        if (t == 0) {
            float a2 = 0.f;
            for (int e = 0; e < NH; e++) a2 += Wk[d * NH + e] * bi[e];
            g_kb[d] = a2;
        }
    } else {
        int e = t;
        float acc = 0.f;
        #pragma unroll 4
        for (int d = 0; d < NH; d++)
            acc += __ldg(&bi[d]) * __ldg(&Wk[d * NH + e]);
        g_q[e] = acc;
    }
}

// ---------------- stage 0b: A (transposed into g_M), v, w, c0 ------
__global__ void small2_kernel(const float* __restrict__ Wi,
                              const float* __restrict__ bi,
                              const float* __restrict__ bk) {
    int b = blockIdx.x;
    int t = threadIdx.x;
    if (b < NH) {
        int k = b;
        float acc = 0.f;
        #pragma unroll 4
        for (int d = 0; d < NH; d++)
            acc += __ldg(&Wi[d * NH + k]) * g_B1[d * NH + t];
        // A[k][t] stored transposed: g_M[t*NH + k]
        g_M[t * NH + k] = acc;
        if (t == 0) {
            float vv = 0.f;
            for (int d = 0; d < NH; d++) vv += Wi[d * NH + k] * g_kb[d];
            g_v[k] = vv;
        }
    } else {
        float acc = 0.f;
        #pragma unroll 4
        for (int e = 0; e < NH; e++)
            acc += g_q[e] * __ldg(&Wi[e * NH + t]);
        g_w[t] = acc;
        if (t == 0) {
            float c = bk[0];
            for (int e = 0; e < NH; e++) c += g_q[e] * bi[e];
            g_c0 = c;
        }
    }
}

// ---------------- stage 1: exclusive scan of grid_sizes ------------
__global__ void scan_kernel(const int* __restrict__ sizes, int G) {
    __shared__ int wsum[32];
    __shared__ int carry;
    int tid = threadIdx.x, lane = tid & 31, wid = tid >> 5;
    if (tid == 0) { carry = 0; g_off[0] = 0; }
    __syncthreads();
    for (int base = 0; base < G; base += 1024) {
        int c = carry;
        int v = (base + tid < G) ? sizes[base + tid] : 0;
        int iv = v;
        #pragma unroll
        for (int o = 1; o < 32; o <<= 1) {
            int tt = __shfl_up_sync(0xFFFFFFFFu, iv, o);
            if (lane >= o) iv += tt;
        }
        if (lane == 31) wsum[wid] = iv;
        __syncthreads();
        if (wid == 0) {
            int s = wsum[lane];
            #pragma unroll
            for (int o = 1; o < 32; o <<= 1) {
                int tt = __shfl_up_sync(0xFFFFFFFFu, s, o);
                if (lane >= o) s += tt;
            }
            wsum[lane] = s;
        }
        __syncthreads();
        int incl = iv + (wid ? wsum[wid - 1] : 0);
        if (base + tid < G) g_off[base + tid + 1] = c + incl;
        int tot = wsum[31];
        __syncthreads();
        if (tid == 0) carry = c + tot;
        __syncthreads();
    }
}

// ---------------- stage 2: per-grid raw segment mean + seg ids -----
__global__ void segmean_kernel(const float* __restrict__ emb_,
                               const int* __restrict__ pos) {
    int g = blockIdx.x;
    int k = threadIdx.x;   // 128 threads: one per dim
    int s0 = g_off[g], s1 = g_off[g + 1];
    int cnt = s1 - s0;
    float acc = 0.f;
    #pragma unroll 4
    for (int j = s0; j < s1; j++) {
        int idx = __ldg(&pos[j]);
        acc += __ldg(&emb_[(size_t)idx * NH + k]);
    }
    float inv = (cnt > 0) ? (1.f / (float)cnt) : 0.f;
    g_S[g * NH + k] = acc * inv;
    for (int j = s0 + k; j < s1; j += NH) g_seg[j] = g;
}

// ---------------- stage 3: U = S @ A^T + v, C = S @ w + c0 ---------
#define GB 16
#define K3_SMEM ((NH * NH + GB * NH + 2 * NH) * 4)
__global__ void ucvec_kernel(int G) {
    extern __shared__ float sm[];
    float* Ms = sm;                    // NH*NH, Ms[k*NH+d] = A[d][k]
    float* sS = sm + NH * NH;          // GB*NH
    float* vs = sS + GB * NH;          // NH
    float* ws = vs + NH;               // NH
    int tid = threadIdx.x;             // 256 threads
    int g0 = blockIdx.x * GB;

    for (int i = tid; i < NH * NH; i += 256) Ms[i] = g_M[i];
    for (int i = tid; i < GB * NH; i += 256) {
        int g = g0 + (i >> 7);
        sS[i] = (g < G) ? g_S[g * NH + (i & 127)] : 0.f;
    }
    if (tid < NH) { vs[tid] = g_v[tid]; ws[tid] = g_w[tid]; }
    __syncthreads();

    int d  = tid & 127;
    int gh = tid >> 7;                 // 0/1, each half handles 8 grids
    float acc[8];
    #pragma unroll
    for (int i = 0; i < 8; i++) acc[i] = vs[d];
    const float* sbase = sS + gh * 8 * NH;
    #pragma unroll 4
    for (int k = 0; k < NH; k++) {
        float m = Ms[k * NH + d];      // conflict-free across d
        #pragma unroll
        for (int i = 0; i < 8; i++) acc[i] += m * sbase[i * NH + k];  // broadcast
    }
    #pragma unroll
    for (int i = 0; i < 8; i++) {
        int g = g0 + gh * 8 + i;
        if (g < G) g_U[g * NH + d] = acc[i];
    }
    if (tid < GB) {
        int g = g0 + tid;
        if (g < G) {
            float c = g_c0;
            const float* s = sS + tid * NH;
            #pragma unroll 4
            for (int k = 0; k < NH; k++) c += ws[k] * s[k];
            g_C[g] = c;
        }
    }
}

// ---------------- stage 4: logits (warp per sample) ----------------
__global__ void logits_kernel(const float* __restrict__ emb,
                              const int* __restrict__ pos,
                              const int* __restrict__ neg,
                              float* __restrict__ out,
                              int P, int total, int ratio) {
    int warp = (blockIdx.x * blockDim.x + threadIdx.x) >> 5;
    int lane = threadIdx.x & 31;
    if (warp >= total) return;
    int idx, g;
    if (warp < P) {
        idx = __ldg(&pos[warp]);
        g = g_seg[warp];
    } else {
        int m = warp - P;
        idx = __ldg(&neg[m]);
        g = g_seg[m / ratio];
    }
    const float4* x = (const float4*)(emb + (size_t)idx * NH);
    const float4* u = (const float4*)(g_U + (size_t)g * NH);
    float4 a = __ldg(&x[lane]);
    float4 b = u[lane];
    float dot = a.x * b.x + a.y * b.y + a.z * b.z + a.w * b.w;
    #pragma unroll
    for (int o = 16; o; o >>= 1) dot += __shfl_down_sync(0xFFFFFFFFu, dot, o);
    if (lane == 0) out[warp] = dot + g_C[g];
}

// ---------------- launch ----------------
extern "C" void kernel_launch(void* const* d_in, const int* in_sizes, int n_in,
                              void* d_out, int out_size) {
    const float* embedding  = (const float*)d_in[0];
    const float* embedding_ = (const float*)d_in[1];
    const int*   grid_sizes = (const int*)d_in[2];
    const int*   pos        = (const int*)d_in[3];
    const int*   neg        = (const int*)d_in[4];
    const float* Wi         = (const float*)d_in[5];
    const float* bi         = (const float*)d_in[6];
    const float* Wk         = (const float*)d_in[7];
    const float* bk         = (const float*)d_in[8];
    float* out = (float*)d_out;

    int G  = in_sizes[2];
    int P  = in_sizes[3];
    int PN = in_sizes[4];
    int ratio = PN / P;
    int total = P + PN;

    cudaFuncSetAttribute(ucvec_kernel,
                         cudaFuncAttributeMaxDynamicSharedMemorySize, K3_SMEM);

    small1_kernel<<<NH + 1, NH>>>(Wi, Wk, bi);
    small2_kernel<<<NH + 1, NH>>>(Wi, bi, bk);
    scan_kernel<<<1, 1024>>>(grid_sizes, G);
    segmean_kernel<<<G, NH>>>(embedding_, pos);
    ucvec_kernel<<<(G + GB - 1) / GB, 256, K3_SMEM>>>(G);
    logits_kernel<<<(total + 7) / 8, 256>>>(embedding, pos, neg, out, P, total, ratio);
}

// round 5
// speedup vs baseline: 1.4569x; 1.4569x over previous
#include <cuda_runtime.h>

#define NH 128
#define MAXG 16384
#define MAXP 524288

// ---------------- scratch (no allocations allowed) ----------------
__device__ __align__(16) float g_S[MAXG * NH];   // per-grid raw segment means
__device__ __align__(16) float g_U[MAXG * NH];   // per-grid u vectors
__device__ float g_C[MAXG];                      // per-grid scalar offset
__device__ int   g_off[MAXG + 1];                // exclusive prefix of grid_sizes
__device__ int   g_seg[MAXP];                    // seg id per pos sample
__device__ float g_B1[NH * NH];                  // Wk @ Wi
__device__ float g_kb[NH];                       // Wk @ bi
__device__ float g_q[NH];                        // bi^T Wk
__device__ __align__(16) float g_M[NH * NH];     // M[k*NH+d] = A[d][k], A = Wi^T Wk Wi
__device__ float g_v[NH];                        // Wi^T Wk bi
__device__ float g_w[NH];                        // Wi^T Wk^T bi
__device__ float g_c0;                           // bi^T Wk bi + bk

// ---------------- stage 0a: B1 = Wk@Wi, kb = Wk@bi, q = bi^T Wk ----
__global__ void small1_kernel(const float* __restrict__ Wi,
                              const float* __restrict__ Wk,
                              const float* __restrict__ bi) {
    int b = blockIdx.x;
    int t = threadIdx.x;
    if (b < NH) {
        int d = b;
        float acc = 0.f;
        #pragma unroll 4
        for (int e = 0; e < NH; e++)
            acc += __ldg(&Wk[d * NH + e]) * __ldg(&Wi[e * NH + t]);
        g_B1[d * NH + t] = acc;
        if (t == 0) {
            float a2 = 0.f;
            for (int e = 0; e < NH; e++) a2 += Wk[d * NH + e] * bi[e];
            g_kb[d] = a2;
        }
    } else {
        int e = t;
        float acc = 0.f;
        #pragma unroll 4
        for (int d = 0; d < NH; d++)
            acc += __ldg(&bi[d]) * __ldg(&Wk[d * NH + e]);
        g_q[e] = acc;
    }
}

// ---------------- stage 0b: A (transposed into g_M), v, w, c0 ------
__global__ void small2_kernel(const float* __restrict__ Wi,
                              const float* __restrict__ bi,
                              const float* __restrict__ bk) {
    int b = blockIdx.x;
    int t = threadIdx.x;
    if (b < NH) {
        int k = b;
        float acc = 0.f;
        #pragma unroll 4
        for (int d = 0; d < NH; d++)
            acc += __ldg(&Wi[d * NH + k]) * g_B1[d * NH + t];
        // A[k][t] stored transposed: g_M[t*NH + k]
        g_M[t * NH + k] = acc;
        if (t == 0) {
            float vv = 0.f;
            for (int d = 0; d < NH; d++) vv += Wi[d * NH + k] * g_kb[d];
            g_v[k] = vv;
        }
    } else {
        float acc = 0.f;
        #pragma unroll 4
        for (int e = 0; e < NH; e++)
            acc += g_q[e] * __ldg(&Wi[e * NH + t]);
        g_w[t] = acc;
        if (t == 0) {
            float c = bk[0];
            for (int e = 0; e < NH; e++) c += g_q[e] * bi[e];
            g_c0 = c;
        }
    }
}

// ---------------- stage 1: single-pass exclusive scan of sizes -----
// Each of 1024 threads owns `per` contiguous elements. One block scan.
__global__ void scan_kernel(const int* __restrict__ sizes, int G) {
    __shared__ int wsum[32];
    int tid = threadIdx.x, lane = tid & 31, wid = tid >> 5;
    int per = (G + 1023) >> 10;           // <= 16 for G <= 16384
    int base = tid * per;
    int local[16];
    int s = 0;
    #pragma unroll
    for (int i = 0; i < 16; i++) {
        int v = (i < per && base + i < G) ? __ldg(&sizes[base + i]) : 0;
        local[i] = v;
        s += v;
    }
    // inclusive warp scan of per-thread sums
    int iv = s;
    #pragma unroll
    for (int o = 1; o < 32; o <<= 1) {
        int tt = __shfl_up_sync(0xFFFFFFFFu, iv, o);
        if (lane >= o) iv += tt;
    }
    if (lane == 31) wsum[wid] = iv;
    __syncthreads();
    if (wid == 0) {
        int w = wsum[lane];
        #pragma unroll
        for (int o = 1; o < 32; o <<= 1) {
            int tt = __shfl_up_sync(0xFFFFFFFFu, w, o);
            if (lane >= o) w += tt;
        }
        wsum[lane] = w;
    }
    __syncthreads();
    int excl = iv - s + (wid ? wsum[wid - 1] : 0);
    int run = excl;
    #pragma unroll
    for (int i = 0; i < 16; i++) {
        if (i < per && base + i < G) {
            g_off[base + i] = run;
            run += local[i];
        }
    }
    if (base < G && base + per >= G) g_off[G] = run;  // total
}

// ---------------- stage 2: per-grid raw segment mean + seg ids -----
// 256 threads: warp w handles rows s0+w, s0+w+8, ...; lane loads float4.
__global__ void __launch_bounds__(256) segmean_kernel(
        const float* __restrict__ emb_,
        const int* __restrict__ pos) {
    __shared__ float4 red[8][32];
    int g = blockIdx.x;
    int tid = threadIdx.x;
    int lane = tid & 31, w = tid >> 5;
    int s0 = g_off[g], s1 = g_off[g + 1];
    int cnt = s1 - s0;

    float4 acc = make_float4(0.f, 0.f, 0.f, 0.f);
    int j = s0 + w;
    int idx = (j < s1) ? __ldg(&pos[j]) : 0;
    while (j < s1) {
        int jn = j + 8;
        int idxn = (jn < s1) ? __ldg(&pos[jn]) : 0;   // prefetch next index
        float4 a = __ldg((const float4*)(emb_ + (size_t)idx * NH) + lane);
        acc.x += a.x; acc.y += a.y; acc.z += a.z; acc.w += a.w;
        idx = idxn; j = jn;
    }
    red[w][lane] = acc;
    __syncthreads();

    if (tid < 32) {
        float4 v = red[0][tid];
        #pragma unroll
        for (int ww = 1; ww < 8; ww++) {
            float4 a = red[ww][tid];
            v.x += a.x; v.y += a.y; v.z += a.z; v.w += a.w;
        }
        float inv = (cnt > 0) ? (1.f / (float)cnt) : 0.f;
        v.x *= inv; v.y *= inv; v.z *= inv; v.w *= inv;
        ((float4*)(g_S + (size_t)g * NH))[tid] = v;
    }
    for (int p = s0 + tid; p < s1; p += 256) g_seg[p] = g;
}

// ---------------- stage 3: U = S @ A^T + v, C = S @ w + c0 ---------
#define GB 16
#define K3_SMEM ((NH * NH + GB * NH + 2 * NH) * 4)
__global__ void ucvec_kernel(int G) {
    extern __shared__ float sm[];
    float* Ms = sm;                    // NH*NH, Ms[k*NH+d] = A[d][k]
    float* sS = sm + NH * NH;          // GB*NH
    float* vs = sS + GB * NH;          // NH
    float* ws = vs + NH;               // NH
    int tid = threadIdx.x;             // 256 threads
    int g0 = blockIdx.x * GB;

    for (int i = tid; i < (NH * NH) / 4; i += 256)
        ((float4*)Ms)[i] = ((const float4*)g_M)[i];
    for (int i = tid; i < (GB * NH) / 4; i += 256) {
        int g = g0 + (i >> 5);
        ((float4*)sS)[i] = (g < G) ? ((const float4*)g_S)[(size_t)g * (NH / 4) + (i & 31)]
                                   : make_float4(0.f, 0.f, 0.f, 0.f);
    }
    if (tid < NH) { vs[tid] = g_v[tid]; ws[tid] = g_w[tid]; }
    __syncthreads();

    int d  = tid & 127;
    int gh = tid >> 7;                 // 0/1, each half handles 8 grids
    float acc[8];
    #pragma unroll
    for (int i = 0; i < 8; i++) acc[i] = vs[d];
    const float* sbase = sS + gh * 8 * NH;
    #pragma unroll 4
    for (int k = 0; k < NH; k++) {
        float m = Ms[k * NH + d];      // conflict-free across d
        #pragma unroll
        for (int i = 0; i < 8; i++) acc[i] += m * sbase[i * NH + k];  // broadcast
    }
    #pragma unroll
    for (int i = 0; i < 8; i++) {
        int g = g0 + gh * 8 + i;
        if (g < G) g_U[(size_t)g * NH + d] = acc[i];
    }
    if (tid < GB) {
        int g = g0 + tid;
        if (g < G) {
            float c = g_c0;
            const float* s = sS + tid * NH;
            #pragma unroll 4
            for (int k = 0; k < NH; k++) c += ws[k] * s[k];
            g_C[g] = c;
        }
    }
}

// ---------------- stage 4: logits (4 samples per warp) -------------
// 8 lanes per sample; each lane does 4 independent float4 loads per table
// (8 outstanding LDG.128 per lane). 3 shuffles per warp reduce all 4 samples.
__global__ void __launch_bounds__(256) logits_kernel(
        const float* __restrict__ emb,
        const int* __restrict__ pos,
        const int* __restrict__ neg,
        float* __restrict__ out,
        int P, int total, int ratio) {
    int t = blockIdx.x * blockDim.x + threadIdx.x;
    int warp = t >> 5;
    int lane = threadIdx.x & 31;
    int sl = lane & 7;                 // lane within sample group
    int sm = warp * 4 + (lane >> 3);   // sample id
    int smc = (sm < total) ? sm : (total - 1);

    int idx, g;
    if (smc < P) {
        idx = __ldg(&pos[smc]);
        g = g_seg[smc];
    } else {
        int m = smc - P;
        idx = __ldg(&neg[m]);
        g = g_seg[m / ratio];
    }

    const float4* x = (const float4*)(emb + (size_t)idx * NH);
    const float4* u = (const float4*)(g_U + (size_t)g * NH);

    float4 a0 = __ldg(&x[sl]);
    float4 a1 = __ldg(&x[sl + 8]);
    float4 a2 = __ldg(&x[sl + 16]);
    float4 a3 = __ldg(&x[sl + 24]);
    float4 b0 = __ldg(&u[sl]);
    float4 b1 = __ldg(&u[sl + 8]);
    float4 b2 = __ldg(&u[sl + 16]);
    float4 b3 = __ldg(&u[sl + 24]);

    float acc = a0.x * b0.x + a0.y * b0.y + a0.z * b0.z + a0.w * b0.w;
    acc += a1.x * b1.x + a1.y * b1.y + a1.z * b1.z + a1.w * b1.w;
    acc += a2.x * b2.x + a2.y * b2.y + a2.z * b2.z + a2.w * b2.w;
    acc += a3.x * b3.x + a3.y * b3.y + a3.z * b3.z + a3.w * b3.w;

    acc += __shfl_down_sync(0xFFFFFFFFu, acc, 4);
    acc += __shfl_down_sync(0xFFFFFFFFu, acc, 2);
    acc += __shfl_down_sync(0xFFFFFFFFu, acc, 1);

    if (sl == 0 && sm < total) out[sm] = acc + g_C[g];
}

// ---------------- launch ----------------
extern "C" void kernel_launch(void* const* d_in, const int* in_sizes, int n_in,
                              void* d_out, int out_size) {
    const float* embedding  = (const float*)d_in[0];
    const float* embedding_ = (const float*)d_in[1];
    const int*   grid_sizes = (const int*)d_in[2];
    const int*   pos        = (const int*)d_in[3];
    const int*   neg        = (const int*)d_in[4];
    const float* Wi         = (const float*)d_in[5];
    const float* bi         = (const float*)d_in[6];
    const float* Wk         = (const float*)d_in[7];
    const float* bk         = (const float*)d_in[8];
    float* out = (float*)d_out;

    int G  = in_sizes[2];
    int P  = in_sizes[3];
    int PN = in_sizes[4];
    int ratio = PN / P;
    int total = P + PN;

    cudaFuncSetAttribute(ucvec_kernel,
                         cudaFuncAttributeMaxDynamicSharedMemorySize, K3_SMEM);

    small1_kernel<<<NH + 1, NH>>>(Wi, Wk, bi);
    small2_kernel<<<NH + 1, NH>>>(Wi, bi, bk);
    scan_kernel<<<1, 1024>>>(grid_sizes, G);
    segmean_kernel<<<G, 256>>>(embedding_, pos);
    ucvec_kernel<<<(G + GB - 1) / GB, 256, K3_SMEM>>>(G);
    // 4 samples per warp, 8 warps per block -> 32 samples per block
    logits_kernel<<<(total + 31) / 32, 256>>>(embedding, pos, neg, out, P, total, ratio);
}